// round 14
// baseline (speedup 1.0000x reference)
#include <cuda_runtime.h>
#include <cuda_bf16.h>

// ---------------- static device scratch ------------------------------------
__device__ int   g_grid[2600000];      // 4 scale grids packed (zero-init, never cleared)
__device__ float g_bufA[6300000];
__device__ float g_bufB[6300000];
__device__ float g_sums[12 * 256];     // per layer: [0:C) sum, [C:2C) sumsq
__device__ float g_wT[710592];         // weights as (tap, q=ci/4, co, ci%4)
__device__ int   g_nb[13500000];       // all 8 neighbor maps, disjoint regions

__device__ __forceinline__ void ffma2(unsigned long long& d,
                                      unsigned long long a,
                                      unsigned long long b) {
    asm("fma.rn.f32x2 %0, %1, %2, %0;" : "+l"(d) : "l"(a), "l"(b));
}

// ---------------- setup kernels ---------------------------------------------
struct WPtrs { const float* w[12]; };

#define WTOT 710592

// weights (taps, ci, co) -> (tap, ci/4, co, ci%4); also zeroes all layer stats
__global__ void k_wtrans_all(WPtrs ws, float* __restrict__ wt,
                             float* __restrict__ sums) {
    const int CI[12] = {4,16,16,32,32,32,64,64,64,64,64,64};
    const int CO[12] = {16,16,32,32,32,64,64,64,64,64,64,128};
    const int TP[12] = {27,27,27,27,27,27,27,27,27,27,27,3};
    int i = blockIdx.x * blockDim.x + threadIdx.x;
    if (i >= WTOT) {
        int r = i - WTOT;
        if (r < 12 * 256) sums[r] = 0.f;
        return;
    }
    int off = 0, l, sz = 0;
    for (l = 0; l < 12; l++) {
        sz = TP[l] * CI[l] * CO[l];
        if (i < off + sz) break;
        off += sz;
    }
    int j  = i - off;
    int co = j % CO[l];
    int r  = j / CO[l];
    int ci = r % CI[l];
    int t  = r / CI[l];
    int dst = (((t * (CI[l] >> 2) + (ci >> 2)) * CO[l] + co) << 2) + (ci & 3);
    wt[off + dst] = ws.w[l][j];
}

// all 4 coordinate scatters in one launch
struct ScAll {
    const int4* coords[4];
    int*        grid[4];
    int base[5];
    int D[4], H[4], W[4];
};
__global__ void k_scatter_all(ScAll a, int total) {
    int i = blockIdx.x * blockDim.x + threadIdx.x;
    if (i >= total) return;
    int s = 0;
    while (i >= a.base[s + 1]) s++;
    int p = i - a.base[s];
    int4 c = __ldg(&a.coords[s][p]);
    a.grid[s][((c.x * a.D[s] + c.y) * a.H[s] + c.z) * a.W[s] + c.w] = p;
}

// all 8 neighbor-map configs in one launch, point-major (one thread = one
// output point, all taps). grid never cleared; zero-init + idempotent scatter
// means stale entries are rejected by coordinate compare.
struct NbCfg {
    const int4* outc;
    const int4* inc;
    const int*  grid;
    long nboff;
    int n_out, KH, KW;
    int sz, sy, sx, pz, py, px, D, H, W;
};
struct NbAll { NbCfg c[8]; int base[9]; };

__global__ void k_nbmap_all(NbAll a, int total, int* __restrict__ nb) {
    int i = blockIdx.x * blockDim.x + threadIdx.x;
    if (i >= total) return;
    int cf = 0;
    while (i >= a.base[cf + 1]) cf++;
    NbCfg c = a.c[cf];
    int pt = i - a.base[cf];
    int4 oc = __ldg(&c.outc[pt]);
    int tap = 0;
    for (int kz = 0; kz < 3; kz++)
        for (int ky = 0; ky < c.KH; ky++)
            for (int kx = 0; kx < c.KW; kx++, tap++) {
                int iz = oc.y * c.sz + kz - c.pz;
                int iy = oc.z * c.sy + ky - c.py;
                int ix = oc.w * c.sx + kx - c.px;
                int idx = -1;
                if (iz >= 0 && iz < c.D && iy >= 0 && iy < c.H &&
                    ix >= 0 && ix < c.W) {
                    int j = __ldg(&c.grid[((oc.x * c.D + iz) * c.H + iy) * c.W + ix]);
                    int4 cc = __ldg(&c.inc[j]);
                    if (cc.x == oc.x && cc.y == iz && cc.z == iy && cc.w == ix)
                        idx = j;
                }
                nb[c.nboff + (long)tap * c.n_out + pt] = idx;
            }
}

// ---------------- templated gather conv (BN+ReLU of prev layer fused) -------
// Block: THREADS threads. co = tid % CT, row = tid / CT. Each row owns PBLK
// points; each thread accumulates NCO = COUT/CT output channels per point.
// Tap indices preloaded to smem. WS: double-buffered weight panels in smem.
// PSKIP: per-point tap skip (p-outer compute) for mid-density layers — the
// idx[p] branch is uniform across the CT threads of a row.
template<int CIN, int COUT, int CT, int PBLK, int TAPS, bool WS, int THREADS,
         bool PSKIP>
__global__ void __launch_bounds__(THREADS)
k_conv_t(const float* __restrict__ fin, float* __restrict__ fout,
         const int* __restrict__ nb, const float* __restrict__ wT,
         const float* __restrict__ psum, const float* __restrict__ pg,
         const float* __restrict__ pb, int n_prev,
         float* __restrict__ sums, int n_out) {
    constexpr int C4  = CIN / 4;
    constexpr int NCO = COUT / CT;
    constexpr int BY  = THREADS / CT;
    constexpr int PTS = BY * PBLK;     // points per block (power of two)
    constexpr int PANEL = C4 * COUT;   // float4 per weight panel
    constexpr int WPANEL = WS ? (2 * PANEL) : 1;
    constexpr int WLOAD  = WS ? ((PANEL + THREADS - 1) / THREADS) : 1;

    __shared__ float4 ssc4[C4], ssh4[C4];
    __shared__ float  bsum[2 * COUT];
    __shared__ float4 fsh[BY][PBLK * C4];
    __shared__ int    sidx[TAPS][PTS];
    __shared__ float4 wsh[WPANEL];

    const int tid = threadIdx.x;
    const int blkbase = blockIdx.x * PTS;
    const bool relu = (n_prev > 0);   // layer 0 input is raw: NO ReLU
    if (tid < CIN) {
        float sc = 1.f, sh = 0.f;
        if (relu) {
            float inv = 1.f / (float)n_prev;
            float mu  = psum[tid] * inv;
            float var = psum[CIN + tid] * inv - mu * mu;
            sc = pg[tid] * rsqrtf(var + 0.001f);
            sh = pb[tid] - mu * sc;
        }
        ((float*)ssc4)[tid] = sc;
        ((float*)ssh4)[tid] = sh;
    }
    for (int i = tid; i < 2 * COUT; i += THREADS) bsum[i] = 0.f;

    const float4* wT4 = (const float4*)wT;
    if (WS) {
#pragma unroll
        for (int i = 0; i < WLOAD; i++) {
            int o = i * THREADS + tid;
            if (PANEL % THREADS == 0 || o < PANEL)
                wsh[o] = __ldg(&wT4[o]);   // panel 0
        }
    }

    // cooperative preload of all tap indices (full MLP, one L2 round trip)
    for (int i = tid; i < TAPS * PTS; i += THREADS) {
        int tap = i / PTS;
        int p   = i & (PTS - 1);
        int pt  = blkbase + p;
        ((int*)sidx)[i] = (pt < n_out)
            ? __ldg(&nb[(size_t)tap * n_out + pt]) : -1;
    }
    __syncthreads();

    const int co  = tid & (CT - 1);
    const int row = tid / CT;
    const int base = blkbase + row * PBLK;
    const float4* fin4 = (const float4*)fin;

    unsigned long long acc[PBLK][NCO];
#pragma unroll
    for (int p = 0; p < PBLK; p++)
#pragma unroll
        for (int j = 0; j < NCO; j++) acc[p][j] = 0ull;

    int cur = 0;
    for (int tap = 0; tap < TAPS; tap++) {
        float4 wreg[WLOAD];
        if (WS && tap + 1 < TAPS) {
#pragma unroll
            for (int i = 0; i < WLOAD; i++) {
                int o = i * THREADS + tid;
                if (PANEL % THREADS == 0 || o < PANEL)
                    wreg[i] = __ldg(&wT4[(size_t)(tap + 1) * PANEL + o]);
            }
        }
        int idx[PBLK];
        bool any = false;
#pragma unroll
        for (int p = 0; p < PBLK; p++) {
            idx[p] = sidx[tap][row * PBLK + p];
            any |= (idx[p] >= 0);
        }
        if (any) {   // stage only when this row has active inputs this tap
#pragma unroll
            for (int t = co; t < PBLK * C4; t += CT) {
                int p = t / C4;
                int q = t & (C4 - 1);
                int ii = idx[p];
                if (ii >= 0) {
                    float4 r  = fin4[(size_t)ii * C4 + q];
                    float4 sc = ssc4[q], sh = ssh4[q];
                    float4 v;
                    v.x = fmaf(r.x, sc.x, sh.x);
                    v.y = fmaf(r.y, sc.y, sh.y);
                    v.z = fmaf(r.z, sc.z, sh.z);
                    v.w = fmaf(r.w, sc.w, sh.w);
                    if (relu) {
                        v.x = fmaxf(v.x, 0.f);
                        v.y = fmaxf(v.y, 0.f);
                        v.z = fmaxf(v.z, 0.f);
                        v.w = fmaxf(v.w, 0.f);
                    }
                    fsh[row][t] = v;
                } else if (!PSKIP) {
                    fsh[row][t] = make_float4(0.f, 0.f, 0.f, 0.f);
                }
            }
        }
        __syncwarp();
        if (PSKIP) {
            // per-point skip: branch uniform across the CT threads of a row
#pragma unroll
            for (int p = 0; p < PBLK; p++) {
                if (idx[p] >= 0) {
#pragma unroll
                    for (int q = 0; q < C4; q++) {
                        ulonglong2 wv[NCO];
#pragma unroll
                        for (int j = 0; j < NCO; j++) {
                            if (WS) {
                                wv[j] = *(const ulonglong2*)
                                    &wsh[cur * PANEL + q * COUT + j * CT + co];
                            } else {
                                float4 w4 = __ldg(&wT4[(size_t)(tap * C4 + q) * COUT + j * CT + co]);
                                wv[j] = *(ulonglong2*)&w4;
                            }
                        }
                        ulonglong2 fv = *(ulonglong2*)&fsh[row][p * C4 + q];
#pragma unroll
                        for (int j = 0; j < NCO; j++) {
                            ffma2(acc[p][j], fv.x, wv[j].x);
                            ffma2(acc[p][j], fv.y, wv[j].y);
                        }
                    }
                }
            }
        } else if (any) {
#pragma unroll
            for (int q = 0; q < C4; q++) {
                ulonglong2 wv[NCO];
#pragma unroll
                for (int j = 0; j < NCO; j++) {
                    if (WS) {
                        wv[j] = *(const ulonglong2*)
                            &wsh[cur * PANEL + q * COUT + j * CT + co];
                    } else {
                        float4 w4 = __ldg(&wT4[(size_t)(tap * C4 + q) * COUT + j * CT + co]);
                        wv[j] = *(ulonglong2*)&w4;
                    }
                }
#pragma unroll
                for (int p = 0; p < PBLK; p++) {
                    ulonglong2 fv = *(ulonglong2*)&fsh[row][p * C4 + q];
#pragma unroll
                    for (int j = 0; j < NCO; j++) {
                        ffma2(acc[p][j], fv.x, wv[j].x);
                        ffma2(acc[p][j], fv.y, wv[j].y);
                    }
                }
            }
        }
        if (WS) {
            if (tap + 1 < TAPS) {
#pragma unroll
                for (int i = 0; i < WLOAD; i++) {
                    int o = i * THREADS + tid;
                    if (PANEL % THREADS == 0 || o < PANEL)
                        wsh[(1 - cur) * PANEL + o] = wreg[i];
                }
                __syncthreads();
                cur ^= 1;
            }
        } else {
            __syncwarp();
        }
    }

    // epilogue: raw conv output + per-channel stats
#pragma unroll
    for (int j = 0; j < NCO; j++) {
        float s = 0.f, s2 = 0.f;
#pragma unroll
        for (int p = 0; p < PBLK; p++) {
            int pt = base + p;
            if (pt < n_out) {
                unsigned lo, hi;
                asm("mov.b64 {%0,%1}, %2;" : "=r"(lo), "=r"(hi) : "l"(acc[p][j]));
                float v = __uint_as_float(lo) + __uint_as_float(hi);
                fout[(size_t)pt * COUT + j * CT + co] = v;
                s  += v;
                s2 += v * v;
            }
        }
        atomicAdd(&bsum[j * CT + co], s);
        atomicAdd(&bsum[COUT + j * CT + co], s2);
    }
    __syncthreads();
    for (int i = tid; i < 2 * COUT; i += THREADS)
        atomicAdd(&sums[i], bsum[i]);
}

// final BN+ReLU (layer 11 -> d_out)
__global__ void k_bnrelu(const float* __restrict__ f, const float* __restrict__ sums,
                         const float* __restrict__ g, const float* __restrict__ b,
                         int n, int C, float* __restrict__ out) {
    __shared__ float ssc[128], ssh[128];
    int tid = threadIdx.x;
    if (tid < C) {
        float inv = 1.f / (float)n;
        float mu  = sums[tid] * inv;
        float var = sums[C + tid] * inv - mu * mu;
        float sc  = g[tid] * rsqrtf(var + 0.001f);
        ssc[tid] = sc;
        ssh[tid] = b[tid] - mu * sc;
    }
    __syncthreads();
    int total = n * C;
    for (int idx = blockIdx.x * blockDim.x + tid; idx < total;
         idx += gridDim.x * blockDim.x) {
        int c = idx & (C - 1);
        float v = f[idx] * ssc[c] + ssh[c];
        out[idx] = v > 0.f ? v : 0.f;
    }
}

// ---------------- host orchestration ----------------------------------------
template<int CIN, int COUT, int CT, int PBLK, int TAPS, bool WS, int THREADS,
         bool PSKIP>
static void launch_conv(const float* fin, float* fout, const int* nb,
                        const float* wt, const float* psum, const float* pg,
                        const float* pb, int n_prev, float* sums, int n_out) {
    int ppb = (THREADS / CT) * PBLK;
    int nblk = (n_out + ppb - 1) / ppb;
    k_conv_t<CIN, COUT, CT, PBLK, TAPS, WS, THREADS, PSKIP><<<nblk, THREADS>>>(
        fin, fout, nb, wt, psum, pg, pb, n_prev, sums, n_out);
}

extern "C" void kernel_launch(void* const* d_in, const int* in_sizes, int n_in,
                              void* d_out, int out_size) {
    const float* vf    = (const float*)d_in[0];
    const float* gamma = (const float*)d_in[13];
    const float* beta  = (const float*)d_in[14];
    const int* coords[5];
    int np[5];
    for (int i = 0; i < 5; i++) {
        coords[i] = (const int*)d_in[15 + i];
        np[i]     = in_sizes[15 + i] / 4;
    }

    void* pv;
    cudaGetSymbolAddress(&pv, g_grid); int*   grid = (int*)pv;
    cudaGetSymbolAddress(&pv, g_bufA); float* bufA = (float*)pv;
    cudaGetSymbolAddress(&pv, g_bufB); float* bufB = (float*)pv;
    cudaGetSymbolAddress(&pv, g_sums); float* sums = (float*)pv;
    cudaGetSymbolAddress(&pv, g_wT);   float* wT   = (float*)pv;
    cudaGetSymbolAddress(&pv, g_nb);   int*   nb   = (int*)pv;

    static const int CO[12]   = {16,16,32,32,32,64,64,64,64,64,64,128};
    static const int OFFc[12] = {0,16,32,64,96,128,192,256,320,384,448,512};
    static const int SHP[4][3] = {{41,160,160},{21,80,80},{11,40,40},{5,20,20}};

    long goff[4];
    goff[0] = 0;
    for (int s = 0; s < 3; s++)
        goff[s + 1] = goff[s] + 2L * SHP[s][0] * SHP[s][1] * SHP[s][2];

    // weight offsets (fixed layer dims)
    static const int CIw[12] = {4,16,16,32,32,32,64,64,64,64,64,64};
    static const int TPw[12] = {27,27,27,27,27,27,27,27,27,27,27,3};
    long woff[13];
    woff[0] = 0;
    for (int l = 0; l < 12; l++)
        woff[l + 1] = woff[l] + (long)TPw[l] * CIw[l] * CO[l];

    // #1: weight transpose + stats zeroing
    WPtrs wp;
    for (int l = 0; l < 12; l++) wp.w[l] = (const float*)d_in[1 + l];
    k_wtrans_all<<<(WTOT + 12 * 256 + 255) / 256, 256>>>(wp, wT, sums);

    // #2: all scatters fused
    ScAll sa;
    sa.base[0] = 0;
    for (int s = 0; s < 4; s++) {
        sa.coords[s] = (const int4*)coords[s];
        sa.grid[s]   = grid + goff[s];
        sa.D[s] = SHP[s][0]; sa.H[s] = SHP[s][1]; sa.W[s] = SHP[s][2];
        sa.base[s + 1] = sa.base[s] + np[s];
    }
    int sctot = sa.base[4];
    k_scatter_all<<<(sctot + 255) / 256, 256>>>(sa, sctot);

    // #3: all neighbor maps fused (point-major)
    static const int cfgIn[8]  = {0, 0, 1, 1, 2, 2, 3, 3};
    static const int cfgOut[8] = {0, 1, 1, 2, 2, 3, 3, 4};
    static const int cfgKH[8]  = {3, 3, 3, 3, 3, 3, 3, 1};
    static const int cfgKW[8]  = {3, 3, 3, 3, 3, 3, 3, 1};
    static const int cfgS[8][3] = {{1,1,1},{2,2,2},{1,1,1},{2,2,2},
                                   {1,1,1},{2,2,2},{1,1,1},{2,1,1}};
    static const int cfgP[8][3] = {{1,1,1},{1,1,1},{1,1,1},{1,1,1},
                                   {1,1,1},{0,1,1},{1,1,1},{0,0,0}};
    NbAll na;
    long nbo[9];
    nbo[0] = 0;
    na.base[0] = 0;
    for (int c = 0; c < 8; c++) {
        int s = cfgIn[c];
        int taps = 3 * cfgKH[c] * cfgKW[c];
        na.c[c].outc  = (const int4*)coords[cfgOut[c]];
        na.c[c].inc   = (const int4*)coords[s];
        na.c[c].grid  = grid + goff[s];
        na.c[c].nboff = nbo[c];
        na.c[c].n_out = np[cfgOut[c]];
        na.c[c].KH = cfgKH[c]; na.c[c].KW = cfgKW[c];
        na.c[c].sz = cfgS[c][0]; na.c[c].sy = cfgS[c][1]; na.c[c].sx = cfgS[c][2];
        na.c[c].pz = cfgP[c][0]; na.c[c].py = cfgP[c][1]; na.c[c].px = cfgP[c][2];
        na.c[c].D = SHP[s][0]; na.c[c].H = SHP[s][1]; na.c[c].W = SHP[s][2];
        nbo[c + 1] = nbo[c] + (long)taps * np[cfgOut[c]];
        na.base[c + 1] = na.base[c] + np[cfgOut[c]];
    }
    int nbtot = na.base[8];
    k_nbmap_all<<<(nbtot + 127) / 128, 128>>>(na, nbtot, nb);

    // per-layer map index
    static const int LMAP[12] = {0, 0, 1, 2, 2, 3, 4, 4, 5, 6, 6, 7};
    static const int ICX[12]  = {0,0,0,1,1,1,2,2,2,3,3,3};
    static const int OCX[12]  = {0,0,1,1,1,2,2,2,3,3,3,4};

    const float* cur = vf;
    float* bufs[2] = {bufA, bufB};
    int cb = 0;

    for (int l = 0; l < 12; l++) {
        int nin  = np[ICX[l]];
        int nout = np[OCX[l]];
        const int* lnb = nb + nbo[LMAP[l]];

        float* outb = bufs[cb];
        const float* psum = (l == 0) ? sums : sums + (l - 1) * 256;
        const float* pg   = (l == 0) ? gamma : gamma + OFFc[l - 1];
        const float* pb   = (l == 0) ? beta  : beta  + OFFc[l - 1];
        int n_prev        = (l == 0) ? 0 : nin;
        float* msum       = sums + l * 256;
        const float* wt   = wT + woff[l];

        // PSKIP on mid-density layers (L2-L5, ~30-50% tap density);
        // dense layers (L6+) keep amortized q-outer structure
        switch (l) {
        case 0:  launch_conv< 4, 16, 16, 2, 27, false, 128, false>(cur, outb, lnb, wt, psum, pg, pb, n_prev, msum, nout); break;
        case 1:  launch_conv<16, 16, 16, 2, 27, false, 128, false>(cur, outb, lnb, wt, psum, pg, pb, n_prev, msum, nout); break;
        case 2:  launch_conv<16, 32, 16, 4, 27, true , 256, true >(cur, outb, lnb, wt, psum, pg, pb, n_prev, msum, nout); break;
        case 3:  launch_conv<32, 32, 16, 8, 27, true , 256, true >(cur, outb, lnb, wt, psum, pg, pb, n_prev, msum, nout); break;
        case 4:  launch_conv<32, 32, 16, 8, 27, true , 256, true >(cur, outb, lnb, wt, psum, pg, pb, n_prev, msum, nout); break;
        case 5:  launch_conv<32, 64, 16, 4, 27, true , 256, true >(cur, outb, lnb, wt, psum, pg, pb, n_prev, msum, nout); break;
        case 6:  launch_conv<64, 64, 16, 4, 27, true , 256, false>(cur, outb, lnb, wt, psum, pg, pb, n_prev, msum, nout); break;
        case 7:  launch_conv<64, 64, 16, 4, 27, true , 256, false>(cur, outb, lnb, wt, psum, pg, pb, n_prev, msum, nout); break;
        case 8:  launch_conv<64, 64, 16, 2, 27, true , 128, false>(cur, outb, lnb, wt, psum, pg, pb, n_prev, msum, nout); break;
        case 9:  launch_conv<64, 64, 16, 2, 27, true , 128, false>(cur, outb, lnb, wt, psum, pg, pb, n_prev, msum, nout); break;
        case 10: launch_conv<64, 64, 16, 2, 27, true , 128, false>(cur, outb, lnb, wt, psum, pg, pb, n_prev, msum, nout); break;
        case 11: launch_conv<64,128, 16, 1,  3, true , 128, false>(cur, outb, lnb, wt, psum, pg, pb, n_prev, msum, nout); break;
        }

        cur = outb;
        cb ^= 1;
    }

    // final BN+ReLU of layer 11 into d_out
    int n5 = np[4];
    int total = n5 * 128;
    int bblk = (total + 255) / 256;
    if (bblk > 2048) bblk = 2048;
    k_bnrelu<<<bblk, 256>>>(cur, sums + 11 * 256, gamma + OFFc[11], beta + OFFc[11],
                            n5, 128, (float*)d_out);
}

// round 15
// speedup vs baseline: 1.1594x; 1.1594x over previous
#include <cuda_runtime.h>
#include <cuda_bf16.h>

// ---------------- static device scratch ------------------------------------
__device__ int   g_grid[2600000];      // 4 scale grids packed (zero-init, never cleared)
__device__ float g_bufA[6300000];
__device__ float g_bufB[6300000];
__device__ float g_sums[12 * 256];     // per layer: [0:C) sum, [C:2C) sumsq
__device__ float g_wT[710592];         // weights as (tap, q=ci/4, co, ci%4)
__device__ int   g_nb[13500000];       // all 8 neighbor maps, disjoint regions

__device__ __forceinline__ void ffma2(unsigned long long& d,
                                      unsigned long long a,
                                      unsigned long long b) {
    asm("fma.rn.f32x2 %0, %1, %2, %0;" : "+l"(d) : "l"(a), "l"(b));
}

// ---------------- setup kernels ---------------------------------------------
struct WPtrs { const float* w[12]; };

#define WTOT 710592

// weights (taps, ci, co) -> (tap, ci/4, co, ci%4); also zeroes all layer stats
__global__ void k_wtrans_all(WPtrs ws, float* __restrict__ wt,
                             float* __restrict__ sums) {
    const int CI[12] = {4,16,16,32,32,32,64,64,64,64,64,64};
    const int CO[12] = {16,16,32,32,32,64,64,64,64,64,64,128};
    const int TP[12] = {27,27,27,27,27,27,27,27,27,27,27,3};
    int i = blockIdx.x * blockDim.x + threadIdx.x;
    if (i >= WTOT) {
        int r = i - WTOT;
        if (r < 12 * 256) sums[r] = 0.f;
        return;
    }
    int off = 0, l, sz = 0;
    for (l = 0; l < 12; l++) {
        sz = TP[l] * CI[l] * CO[l];
        if (i < off + sz) break;
        off += sz;
    }
    int j  = i - off;
    int co = j % CO[l];
    int r  = j / CO[l];
    int ci = r % CI[l];
    int t  = r / CI[l];
    int dst = (((t * (CI[l] >> 2) + (ci >> 2)) * CO[l] + co) << 2) + (ci & 3);
    wt[off + dst] = ws.w[l][j];
}

// all 4 coordinate scatters in one launch
struct ScAll {
    const int4* coords[4];
    int*        grid[4];
    int base[5];
    int D[4], H[4], W[4];
};
__global__ void k_scatter_all(ScAll a, int total) {
    int i = blockIdx.x * blockDim.x + threadIdx.x;
    if (i >= total) return;
    int s = 0;
    while (i >= a.base[s + 1]) s++;
    int p = i - a.base[s];
    int4 c = __ldg(&a.coords[s][p]);
    a.grid[s][((c.x * a.D[s] + c.y) * a.H[s] + c.z) * a.W[s] + c.w] = p;
}

// all 8 neighbor-map configs in one launch, point-major (one thread = one
// output point, all taps). grid never cleared; zero-init + idempotent scatter
// means stale entries are rejected by coordinate compare.
struct NbCfg {
    const int4* outc;
    const int4* inc;
    const int*  grid;
    long nboff;
    int n_out, KH, KW;
    int sz, sy, sx, pz, py, px, D, H, W;
};
struct NbAll { NbCfg c[8]; int base[9]; };

__global__ void k_nbmap_all(NbAll a, int total, int* __restrict__ nb) {
    int i = blockIdx.x * blockDim.x + threadIdx.x;
    if (i >= total) return;
    int cf = 0;
    while (i >= a.base[cf + 1]) cf++;
    NbCfg c = a.c[cf];
    int pt = i - a.base[cf];
    int4 oc = __ldg(&c.outc[pt]);
    int tap = 0;
    for (int kz = 0; kz < 3; kz++)
        for (int ky = 0; ky < c.KH; ky++)
            for (int kx = 0; kx < c.KW; kx++, tap++) {
                int iz = oc.y * c.sz + kz - c.pz;
                int iy = oc.z * c.sy + ky - c.py;
                int ix = oc.w * c.sx + kx - c.px;
                int idx = -1;
                if (iz >= 0 && iz < c.D && iy >= 0 && iy < c.H &&
                    ix >= 0 && ix < c.W) {
                    int j = __ldg(&c.grid[((oc.x * c.D + iz) * c.H + iy) * c.W + ix]);
                    int4 cc = __ldg(&c.inc[j]);
                    if (cc.x == oc.x && cc.y == iz && cc.z == iy && cc.w == ix)
                        idx = j;
                }
                nb[c.nboff + (long)tap * c.n_out + pt] = idx;
            }
}

// ---------------- templated gather conv (BN+ReLU of prev layer fused) -------
// Block: THREADS threads. co = tid % CT, row = tid / CT. Each row owns PBLK
// points; each thread accumulates NCO = COUT/CT output channels per point.
// Tap indices preloaded to smem. WS: double-buffered weight panels in smem
// (prefetch next panel into regs during compute, STS + one barrier per tap).
template<int CIN, int COUT, int CT, int PBLK, int TAPS, bool WS, int THREADS>
__global__ void __launch_bounds__(THREADS)
k_conv_t(const float* __restrict__ fin, float* __restrict__ fout,
         const int* __restrict__ nb, const float* __restrict__ wT,
         const float* __restrict__ psum, const float* __restrict__ pg,
         const float* __restrict__ pb, int n_prev,
         float* __restrict__ sums, int n_out) {
    constexpr int C4  = CIN / 4;
    constexpr int NCO = COUT / CT;
    constexpr int BY  = THREADS / CT;
    constexpr int PTS = BY * PBLK;     // points per block (power of two)
    constexpr int PANEL = C4 * COUT;   // float4 per weight panel
    constexpr int WPANEL = WS ? (2 * PANEL) : 1;
    constexpr int WLOAD  = WS ? ((PANEL + THREADS - 1) / THREADS) : 1;

    __shared__ float4 ssc4[C4], ssh4[C4];
    __shared__ float  bsum[2 * COUT];
    __shared__ float4 fsh[BY][PBLK * C4];
    __shared__ int    sidx[TAPS][PTS];
    __shared__ float4 wsh[WPANEL];

    const int tid = threadIdx.x;
    const int blkbase = blockIdx.x * PTS;
    const bool relu = (n_prev > 0);   // layer 0 input is raw: NO ReLU
    if (tid < CIN) {
        float sc = 1.f, sh = 0.f;
        if (relu) {
            float inv = 1.f / (float)n_prev;
            float mu  = psum[tid] * inv;
            float var = psum[CIN + tid] * inv - mu * mu;
            sc = pg[tid] * rsqrtf(var + 0.001f);
            sh = pb[tid] - mu * sc;
        }
        ((float*)ssc4)[tid] = sc;
        ((float*)ssh4)[tid] = sh;
    }
    for (int i = tid; i < 2 * COUT; i += THREADS) bsum[i] = 0.f;

    const float4* wT4 = (const float4*)wT;
    if (WS) {
#pragma unroll
        for (int i = 0; i < WLOAD; i++) {
            int o = i * THREADS + tid;
            if (PANEL % THREADS == 0 || o < PANEL)
                wsh[o] = __ldg(&wT4[o]);   // panel 0
        }
    }

    // cooperative preload of all tap indices (full MLP, one L2 round trip)
    for (int i = tid; i < TAPS * PTS; i += THREADS) {
        int tap = i / PTS;
        int p   = i & (PTS - 1);
        int pt  = blkbase + p;
        ((int*)sidx)[i] = (pt < n_out)
            ? __ldg(&nb[(size_t)tap * n_out + pt]) : -1;
    }
    __syncthreads();

    const int co  = tid & (CT - 1);
    const int row = tid / CT;
    const int base = blkbase + row * PBLK;
    const float4* fin4 = (const float4*)fin;

    unsigned long long acc[PBLK][NCO];
#pragma unroll
    for (int p = 0; p < PBLK; p++)
#pragma unroll
        for (int j = 0; j < NCO; j++) acc[p][j] = 0ull;

    int cur = 0;
    for (int tap = 0; tap < TAPS; tap++) {
        float4 wreg[WLOAD];
        if (WS && tap + 1 < TAPS) {
#pragma unroll
            for (int i = 0; i < WLOAD; i++) {
                int o = i * THREADS + tid;
                if (PANEL % THREADS == 0 || o < PANEL)
                    wreg[i] = __ldg(&wT4[(size_t)(tap + 1) * PANEL + o]);
            }
        }
        int idx[PBLK];
        bool any = false;
#pragma unroll
        for (int p = 0; p < PBLK; p++) {
            idx[p] = sidx[tap][row * PBLK + p];
            any |= (idx[p] >= 0);
        }
        if (any) {   // stage only when this row has active inputs this tap
#pragma unroll
            for (int t = co; t < PBLK * C4; t += CT) {
                int p = t / C4;
                int q = t & (C4 - 1);
                int ii = idx[p];
                float4 v = make_float4(0.f, 0.f, 0.f, 0.f);
                if (ii >= 0) {
                    float4 r  = fin4[(size_t)ii * C4 + q];
                    float4 sc = ssc4[q], sh = ssh4[q];
                    v.x = fmaf(r.x, sc.x, sh.x);
                    v.y = fmaf(r.y, sc.y, sh.y);
                    v.z = fmaf(r.z, sc.z, sh.z);
                    v.w = fmaf(r.w, sc.w, sh.w);
                    if (relu) {
                        v.x = fmaxf(v.x, 0.f);
                        v.y = fmaxf(v.y, 0.f);
                        v.z = fmaxf(v.z, 0.f);
                        v.w = fmaxf(v.w, 0.f);
                    }
                }
                fsh[row][t] = v;
            }
        }
        __syncwarp();
        if (any) {
#pragma unroll
            for (int q = 0; q < C4; q++) {
                ulonglong2 wv[NCO];
#pragma unroll
                for (int j = 0; j < NCO; j++) {
                    if (WS) {
                        wv[j] = *(const ulonglong2*)
                            &wsh[cur * PANEL + q * COUT + j * CT + co];
                    } else {
                        float4 w4 = __ldg(&wT4[(size_t)(tap * C4 + q) * COUT + j * CT + co]);
                        wv[j] = *(ulonglong2*)&w4;
                    }
                }
#pragma unroll
                for (int p = 0; p < PBLK; p++) {
                    ulonglong2 fv = *(ulonglong2*)&fsh[row][p * C4 + q];
#pragma unroll
                    for (int j = 0; j < NCO; j++) {
                        ffma2(acc[p][j], fv.x, wv[j].x);
                        ffma2(acc[p][j], fv.y, wv[j].y);
                    }
                }
            }
        }
        if (WS) {
            if (tap + 1 < TAPS) {
#pragma unroll
                for (int i = 0; i < WLOAD; i++) {
                    int o = i * THREADS + tid;
                    if (PANEL % THREADS == 0 || o < PANEL)
                        wsh[(1 - cur) * PANEL + o] = wreg[i];
                }
                __syncthreads();
                cur ^= 1;
            }
        } else {
            __syncwarp();
        }
    }

    // epilogue: raw conv output + per-channel stats
#pragma unroll
    for (int j = 0; j < NCO; j++) {
        float s = 0.f, s2 = 0.f;
#pragma unroll
        for (int p = 0; p < PBLK; p++) {
            int pt = base + p;
            if (pt < n_out) {
                unsigned lo, hi;
                asm("mov.b64 {%0,%1}, %2;" : "=r"(lo), "=r"(hi) : "l"(acc[p][j]));
                float v = __uint_as_float(lo) + __uint_as_float(hi);
                fout[(size_t)pt * COUT + j * CT + co] = v;
                s  += v;
                s2 += v * v;
            }
        }
        atomicAdd(&bsum[j * CT + co], s);
        atomicAdd(&bsum[COUT + j * CT + co], s2);
    }
    __syncthreads();
    for (int i = tid; i < 2 * COUT; i += THREADS)
        atomicAdd(&sums[i], bsum[i]);
}

// final BN+ReLU (layer 11 -> d_out)
__global__ void k_bnrelu(const float* __restrict__ f, const float* __restrict__ sums,
                         const float* __restrict__ g, const float* __restrict__ b,
                         int n, int C, float* __restrict__ out) {
    __shared__ float ssc[128], ssh[128];
    int tid = threadIdx.x;
    if (tid < C) {
        float inv = 1.f / (float)n;
        float mu  = sums[tid] * inv;
        float var = sums[C + tid] * inv - mu * mu;
        float sc  = g[tid] * rsqrtf(var + 0.001f);
        ssc[tid] = sc;
        ssh[tid] = b[tid] - mu * sc;
    }
    __syncthreads();
    int total = n * C;
    for (int idx = blockIdx.x * blockDim.x + tid; idx < total;
         idx += gridDim.x * blockDim.x) {
        int c = idx & (C - 1);
        float v = f[idx] * ssc[c] + ssh[c];
        out[idx] = v > 0.f ? v : 0.f;
    }
}

// ---------------- host orchestration ----------------------------------------
template<int CIN, int COUT, int CT, int PBLK, int TAPS, bool WS, int THREADS>
static void launch_conv(const float* fin, float* fout, const int* nb,
                        const float* wt, const float* psum, const float* pg,
                        const float* pb, int n_prev, float* sums, int n_out) {
    int ppb = (THREADS / CT) * PBLK;
    int nblk = (n_out + ppb - 1) / ppb;
    k_conv_t<CIN, COUT, CT, PBLK, TAPS, WS, THREADS><<<nblk, THREADS>>>(
        fin, fout, nb, wt, psum, pg, pb, n_prev, sums, n_out);
}

extern "C" void kernel_launch(void* const* d_in, const int* in_sizes, int n_in,
                              void* d_out, int out_size) {
    const float* vf    = (const float*)d_in[0];
    const float* gamma = (const float*)d_in[13];
    const float* beta  = (const float*)d_in[14];
    const int* coords[5];
    int np[5];
    for (int i = 0; i < 5; i++) {
        coords[i] = (const int*)d_in[15 + i];
        np[i]     = in_sizes[15 + i] / 4;
    }

    void* pv;
    cudaGetSymbolAddress(&pv, g_grid); int*   grid = (int*)pv;
    cudaGetSymbolAddress(&pv, g_bufA); float* bufA = (float*)pv;
    cudaGetSymbolAddress(&pv, g_bufB); float* bufB = (float*)pv;
    cudaGetSymbolAddress(&pv, g_sums); float* sums = (float*)pv;
    cudaGetSymbolAddress(&pv, g_wT);   float* wT   = (float*)pv;
    cudaGetSymbolAddress(&pv, g_nb);   int*   nb   = (int*)pv;

    static const int CO[12]   = {16,16,32,32,32,64,64,64,64,64,64,128};
    static const int OFFc[12] = {0,16,32,64,96,128,192,256,320,384,448,512};
    static const int SHP[4][3] = {{41,160,160},{21,80,80},{11,40,40},{5,20,20}};

    long goff[4];
    goff[0] = 0;
    for (int s = 0; s < 3; s++)
        goff[s + 1] = goff[s] + 2L * SHP[s][0] * SHP[s][1] * SHP[s][2];

    // weight offsets (fixed layer dims)
    static const int CIw[12] = {4,16,16,32,32,32,64,64,64,64,64,64};
    static const int TPw[12] = {27,27,27,27,27,27,27,27,27,27,27,3};
    long woff[13];
    woff[0] = 0;
    for (int l = 0; l < 12; l++)
        woff[l + 1] = woff[l] + (long)TPw[l] * CIw[l] * CO[l];

    // #1: weight transpose + stats zeroing
    WPtrs wp;
    for (int l = 0; l < 12; l++) wp.w[l] = (const float*)d_in[1 + l];
    k_wtrans_all<<<(WTOT + 12 * 256 + 255) / 256, 256>>>(wp, wT, sums);

    // #2: all scatters fused
    ScAll sa;
    sa.base[0] = 0;
    for (int s = 0; s < 4; s++) {
        sa.coords[s] = (const int4*)coords[s];
        sa.grid[s]   = grid + goff[s];
        sa.D[s] = SHP[s][0]; sa.H[s] = SHP[s][1]; sa.W[s] = SHP[s][2];
        sa.base[s + 1] = sa.base[s] + np[s];
    }
    int sctot = sa.base[4];
    k_scatter_all<<<(sctot + 255) / 256, 256>>>(sa, sctot);

    // #3: all neighbor maps fused (point-major)
    static const int cfgIn[8]  = {0, 0, 1, 1, 2, 2, 3, 3};
    static const int cfgOut[8] = {0, 1, 1, 2, 2, 3, 3, 4};
    static const int cfgKH[8]  = {3, 3, 3, 3, 3, 3, 3, 1};
    static const int cfgKW[8]  = {3, 3, 3, 3, 3, 3, 3, 1};
    static const int cfgS[8][3] = {{1,1,1},{2,2,2},{1,1,1},{2,2,2},
                                   {1,1,1},{2,2,2},{1,1,1},{2,1,1}};
    static const int cfgP[8][3] = {{1,1,1},{1,1,1},{1,1,1},{1,1,1},
                                   {1,1,1},{0,1,1},{1,1,1},{0,0,0}};
    NbAll na;
    long nbo[9];
    nbo[0] = 0;
    na.base[0] = 0;
    for (int c = 0; c < 8; c++) {
        int s = cfgIn[c];
        int taps = 3 * cfgKH[c] * cfgKW[c];
        na.c[c].outc  = (const int4*)coords[cfgOut[c]];
        na.c[c].inc   = (const int4*)coords[s];
        na.c[c].grid  = grid + goff[s];
        na.c[c].nboff = nbo[c];
        na.c[c].n_out = np[cfgOut[c]];
        na.c[c].KH = cfgKH[c]; na.c[c].KW = cfgKW[c];
        na.c[c].sz = cfgS[c][0]; na.c[c].sy = cfgS[c][1]; na.c[c].sx = cfgS[c][2];
        na.c[c].pz = cfgP[c][0]; na.c[c].py = cfgP[c][1]; na.c[c].px = cfgP[c][2];
        na.c[c].D = SHP[s][0]; na.c[c].H = SHP[s][1]; na.c[c].W = SHP[s][2];
        nbo[c + 1] = nbo[c] + (long)taps * np[cfgOut[c]];
        na.base[c + 1] = na.base[c] + np[cfgOut[c]];
    }
    int nbtot = na.base[8];
    k_nbmap_all<<<(nbtot + 127) / 128, 128>>>(na, nbtot, nb);

    // per-layer map index
    static const int LMAP[12] = {0, 0, 1, 2, 2, 3, 4, 4, 5, 6, 6, 7};
    static const int ICX[12]  = {0,0,0,1,1,1,2,2,2,3,3,3};
    static const int OCX[12]  = {0,0,1,1,1,2,2,2,3,3,3,4};

    const float* cur = vf;
    float* bufs[2] = {bufA, bufB};
    int cb = 0;

    for (int l = 0; l < 12; l++) {
        int nin  = np[ICX[l]];
        int nout = np[OCX[l]];
        const int* lnb = nb + nbo[LMAP[l]];

        float* outb = bufs[cb];
        const float* psum = (l == 0) ? sums : sums + (l - 1) * 256;
        const float* pg   = (l == 0) ? gamma : gamma + OFFc[l - 1];
        const float* pb   = (l == 0) ? beta  : beta  + OFFc[l - 1];
        int n_prev        = (l == 0) ? 0 : nin;
        float* msum       = sums + l * 256;
        const float* wt   = wT + woff[l];

        // round-13 structure; heavy WS layers get 512-thread blocks to halve
        // weight-panel traffic + per-tap barrier count again (regs unchanged)
        switch (l) {
        case 0:  launch_conv< 4, 16, 16, 2, 27, false, 128>(cur, outb, lnb, wt, psum, pg, pb, n_prev, msum, nout); break;
        case 1:  launch_conv<16, 16, 16, 2, 27, false, 128>(cur, outb, lnb, wt, psum, pg, pb, n_prev, msum, nout); break;
        case 2:  launch_conv<16, 32, 16, 4, 27, true , 256>(cur, outb, lnb, wt, psum, pg, pb, n_prev, msum, nout); break;
        case 3:  launch_conv<32, 32, 16, 8, 27, true , 512>(cur, outb, lnb, wt, psum, pg, pb, n_prev, msum, nout); break;
        case 4:  launch_conv<32, 32, 16, 8, 27, true , 512>(cur, outb, lnb, wt, psum, pg, pb, n_prev, msum, nout); break;
        case 5:  launch_conv<32, 64, 16, 4, 27, true , 512>(cur, outb, lnb, wt, psum, pg, pb, n_prev, msum, nout); break;
        case 6:  launch_conv<64, 64, 16, 4, 27, true , 512>(cur, outb, lnb, wt, psum, pg, pb, n_prev, msum, nout); break;
        case 7:  launch_conv<64, 64, 16, 4, 27, true , 512>(cur, outb, lnb, wt, psum, pg, pb, n_prev, msum, nout); break;
        case 8:  launch_conv<64, 64, 16, 2, 27, true , 128>(cur, outb, lnb, wt, psum, pg, pb, n_prev, msum, nout); break;
        case 9:  launch_conv<64, 64, 16, 2, 27, true , 128>(cur, outb, lnb, wt, psum, pg, pb, n_prev, msum, nout); break;
        case 10: launch_conv<64, 64, 16, 2, 27, true , 128>(cur, outb, lnb, wt, psum, pg, pb, n_prev, msum, nout); break;
        case 11: launch_conv<64,128, 16, 1,  3, true , 128>(cur, outb, lnb, wt, psum, pg, pb, n_prev, msum, nout); break;
        }

        cur = outb;
        cb ^= 1;
    }

    // final BN+ReLU of layer 11 into d_out
    int n5 = np[4];
    int total = n5 * 128;
    int bblk = (total + 255) / 256;
    if (bblk > 2048) bblk = 2048;
    k_bnrelu<<<bblk, 256>>>(cur, sums + 11 * 256, gamma + OFFc[11], beta + OFFc[11],
                            n5, 128, (float*)d_out);
}

// round 16
// speedup vs baseline: 1.3027x; 1.1236x over previous
#include <cuda_runtime.h>
#include <cuda_bf16.h>

// ---------------- static device scratch ------------------------------------
__device__ int   g_grid[2600000];      // 4 scale grids packed (zero-init, never cleared)
__device__ float g_bufA[6300000];
__device__ float g_bufB[6300000];
__device__ float g_sums[12 * 256];     // per layer: [0:C) sum, [C:2C) sumsq
__device__ float g_wT[710592];         // weights as (tap, q=ci/4, co, ci%4)
__device__ int   g_nb[13500000];       // all 8 neighbor maps, disjoint regions

__device__ __forceinline__ void ffma2(unsigned long long& d,
                                      unsigned long long a,
                                      unsigned long long b) {
    asm("fma.rn.f32x2 %0, %1, %2, %0;" : "+l"(d) : "l"(a), "l"(b));
}

// ---------------- setup kernels ---------------------------------------------
struct WPtrs { const float* w[12]; };

#define WTOT 710592

// weights (taps, ci, co) -> (tap, ci/4, co, ci%4); also zeroes all layer stats
__global__ void k_wtrans_all(WPtrs ws, float* __restrict__ wt,
                             float* __restrict__ sums) {
    const int CI[12] = {4,16,16,32,32,32,64,64,64,64,64,64};
    const int CO[12] = {16,16,32,32,32,64,64,64,64,64,64,128};
    const int TP[12] = {27,27,27,27,27,27,27,27,27,27,27,3};
    int i = blockIdx.x * blockDim.x + threadIdx.x;
    if (i >= WTOT) {
        int r = i - WTOT;
        if (r < 12 * 256) sums[r] = 0.f;
        return;
    }
    int off = 0, l, sz = 0;
    for (l = 0; l < 12; l++) {
        sz = TP[l] * CI[l] * CO[l];
        if (i < off + sz) break;
        off += sz;
    }
    int j  = i - off;
    int co = j % CO[l];
    int r  = j / CO[l];
    int ci = r % CI[l];
    int t  = r / CI[l];
    int dst = (((t * (CI[l] >> 2) + (ci >> 2)) * CO[l] + co) << 2) + (ci & 3);
    wt[off + dst] = ws.w[l][j];
}

// all 4 coordinate scatters in one launch
struct ScAll {
    const int4* coords[4];
    int*        grid[4];
    int base[5];
    int D[4], H[4], W[4];
};
__global__ void k_scatter_all(ScAll a, int total) {
    int i = blockIdx.x * blockDim.x + threadIdx.x;
    if (i >= total) return;
    int s = 0;
    while (i >= a.base[s + 1]) s++;
    int p = i - a.base[s];
    int4 c = __ldg(&a.coords[s][p]);
    a.grid[s][((c.x * a.D[s] + c.y) * a.H[s] + c.z) * a.W[s] + c.w] = p;
}

// all 8 neighbor-map configs in one launch, point-major (one thread = one
// output point, all taps). grid never cleared; zero-init + idempotent scatter
// means stale entries are rejected by coordinate compare.
struct NbCfg {
    const int4* outc;
    const int4* inc;
    const int*  grid;
    long nboff;
    int n_out, KH, KW;
    int sz, sy, sx, pz, py, px, D, H, W;
};
struct NbAll { NbCfg c[8]; int base[9]; };

__global__ void k_nbmap_all(NbAll a, int total, int* __restrict__ nb) {
    int i = blockIdx.x * blockDim.x + threadIdx.x;
    if (i >= total) return;
    int cf = 0;
    while (i >= a.base[cf + 1]) cf++;
    NbCfg c = a.c[cf];
    int pt = i - a.base[cf];
    int4 oc = __ldg(&c.outc[pt]);
    int tap = 0;
    for (int kz = 0; kz < 3; kz++)
        for (int ky = 0; ky < c.KH; ky++)
            for (int kx = 0; kx < c.KW; kx++, tap++) {
                int iz = oc.y * c.sz + kz - c.pz;
                int iy = oc.z * c.sy + ky - c.py;
                int ix = oc.w * c.sx + kx - c.px;
                int idx = -1;
                if (iz >= 0 && iz < c.D && iy >= 0 && iy < c.H &&
                    ix >= 0 && ix < c.W) {
                    int j = __ldg(&c.grid[((oc.x * c.D + iz) * c.H + iy) * c.W + ix]);
                    int4 cc = __ldg(&c.inc[j]);
                    if (cc.x == oc.x && cc.y == iz && cc.z == iy && cc.w == ix)
                        idx = j;
                }
                nb[c.nboff + (long)tap * c.n_out + pt] = idx;
            }
}

// ---------------- templated gather conv (BN+ReLU of prev layer fused) -------
// Block: THREADS threads. co = tid % CT, row = tid / CT. Each row owns PBLK
// points; each thread accumulates NCO = COUT/CT output channels per point.
// Tap indices preloaded to smem. WS: double-buffered weight panels in smem
// (prefetch next panel into regs during compute, STS + one barrier per tap).
template<int CIN, int COUT, int CT, int PBLK, int TAPS, bool WS, int THREADS>
__global__ void __launch_bounds__(THREADS)
k_conv_t(const float* __restrict__ fin, float* __restrict__ fout,
         const int* __restrict__ nb, const float* __restrict__ wT,
         const float* __restrict__ psum, const float* __restrict__ pg,
         const float* __restrict__ pb, int n_prev,
         float* __restrict__ sums, int n_out) {
    constexpr int C4  = CIN / 4;
    constexpr int NCO = COUT / CT;
    constexpr int BY  = THREADS / CT;
    constexpr int PTS = BY * PBLK;     // points per block (power of two)
    constexpr int PANEL = C4 * COUT;   // float4 per weight panel
    constexpr int WPANEL = WS ? (2 * PANEL) : 1;
    constexpr int WLOAD  = WS ? ((PANEL + THREADS - 1) / THREADS) : 1;

    __shared__ float4 ssc4[C4], ssh4[C4];
    __shared__ float  bsum[2 * COUT];
    __shared__ float4 fsh[BY][PBLK * C4];
    __shared__ int    sidx[TAPS][PTS];
    __shared__ float4 wsh[WPANEL];

    const int tid = threadIdx.x;
    const int blkbase = blockIdx.x * PTS;
    const bool relu = (n_prev > 0);   // layer 0 input is raw: NO ReLU
    if (tid < CIN) {
        float sc = 1.f, sh = 0.f;
        if (relu) {
            float inv = 1.f / (float)n_prev;
            float mu  = psum[tid] * inv;
            float var = psum[CIN + tid] * inv - mu * mu;
            sc = pg[tid] * rsqrtf(var + 0.001f);
            sh = pb[tid] - mu * sc;
        }
        ((float*)ssc4)[tid] = sc;
        ((float*)ssh4)[tid] = sh;
    }
    for (int i = tid; i < 2 * COUT; i += THREADS) bsum[i] = 0.f;

    const float4* wT4 = (const float4*)wT;
    if (WS) {
#pragma unroll
        for (int i = 0; i < WLOAD; i++) {
            int o = i * THREADS + tid;
            if (PANEL % THREADS == 0 || o < PANEL)
                wsh[o] = __ldg(&wT4[o]);   // panel 0
        }
    }

    // cooperative preload of all tap indices (full MLP, one L2 round trip)
    for (int i = tid; i < TAPS * PTS; i += THREADS) {
        int tap = i / PTS;
        int p   = i & (PTS - 1);
        int pt  = blkbase + p;
        ((int*)sidx)[i] = (pt < n_out)
            ? __ldg(&nb[(size_t)tap * n_out + pt]) : -1;
    }
    __syncthreads();

    const int co  = tid & (CT - 1);
    const int row = tid / CT;
    const int base = blkbase + row * PBLK;
    const float4* fin4 = (const float4*)fin;

    unsigned long long acc[PBLK][NCO];
#pragma unroll
    for (int p = 0; p < PBLK; p++)
#pragma unroll
        for (int j = 0; j < NCO; j++) acc[p][j] = 0ull;

    int cur = 0;
    for (int tap = 0; tap < TAPS; tap++) {
        float4 wreg[WLOAD];
        if (WS && tap + 1 < TAPS) {
#pragma unroll
            for (int i = 0; i < WLOAD; i++) {
                int o = i * THREADS + tid;
                if (PANEL % THREADS == 0 || o < PANEL)
                    wreg[i] = __ldg(&wT4[(size_t)(tap + 1) * PANEL + o]);
            }
        }
        int idx[PBLK];
        bool any = false;
#pragma unroll
        for (int p = 0; p < PBLK; p++) {
            idx[p] = sidx[tap][row * PBLK + p];
            any |= (idx[p] >= 0);
        }
        if (any) {   // stage only when this row has active inputs this tap
#pragma unroll
            for (int t = co; t < PBLK * C4; t += CT) {
                int p = t / C4;
                int q = t & (C4 - 1);
                int ii = idx[p];
                float4 v = make_float4(0.f, 0.f, 0.f, 0.f);
                if (ii >= 0) {
                    float4 r  = fin4[(size_t)ii * C4 + q];
                    float4 sc = ssc4[q], sh = ssh4[q];
                    v.x = fmaf(r.x, sc.x, sh.x);
                    v.y = fmaf(r.y, sc.y, sh.y);
                    v.z = fmaf(r.z, sc.z, sh.z);
                    v.w = fmaf(r.w, sc.w, sh.w);
                    if (relu) {
                        v.x = fmaxf(v.x, 0.f);
                        v.y = fmaxf(v.y, 0.f);
                        v.z = fmaxf(v.z, 0.f);
                        v.w = fmaxf(v.w, 0.f);
                    }
                }
                fsh[row][t] = v;
            }
        }
        __syncwarp();
        if (any) {
#pragma unroll
            for (int q = 0; q < C4; q++) {
                ulonglong2 wv[NCO];
#pragma unroll
                for (int j = 0; j < NCO; j++) {
                    if (WS) {
                        wv[j] = *(const ulonglong2*)
                            &wsh[cur * PANEL + q * COUT + j * CT + co];
                    } else {
                        float4 w4 = __ldg(&wT4[(size_t)(tap * C4 + q) * COUT + j * CT + co]);
                        wv[j] = *(ulonglong2*)&w4;
                    }
                }
#pragma unroll
                for (int p = 0; p < PBLK; p++) {
                    ulonglong2 fv = *(ulonglong2*)&fsh[row][p * C4 + q];
#pragma unroll
                    for (int j = 0; j < NCO; j++) {
                        ffma2(acc[p][j], fv.x, wv[j].x);
                        ffma2(acc[p][j], fv.y, wv[j].y);
                    }
                }
            }
        }
        if (WS) {
            if (tap + 1 < TAPS) {
#pragma unroll
                for (int i = 0; i < WLOAD; i++) {
                    int o = i * THREADS + tid;
                    if (PANEL % THREADS == 0 || o < PANEL)
                        wsh[(1 - cur) * PANEL + o] = wreg[i];
                }
                __syncthreads();
                cur ^= 1;
            }
        } else {
            __syncwarp();
        }
    }

    // epilogue: raw conv output + per-channel stats
#pragma unroll
    for (int j = 0; j < NCO; j++) {
        float s = 0.f, s2 = 0.f;
#pragma unroll
        for (int p = 0; p < PBLK; p++) {
            int pt = base + p;
            if (pt < n_out) {
                unsigned lo, hi;
                asm("mov.b64 {%0,%1}, %2;" : "=r"(lo), "=r"(hi) : "l"(acc[p][j]));
                float v = __uint_as_float(lo) + __uint_as_float(hi);
                fout[(size_t)pt * COUT + j * CT + co] = v;
                s  += v;
                s2 += v * v;
            }
        }
        atomicAdd(&bsum[j * CT + co], s);
        atomicAdd(&bsum[COUT + j * CT + co], s2);
    }
    __syncthreads();
    for (int i = tid; i < 2 * COUT; i += THREADS)
        atomicAdd(&sums[i], bsum[i]);
}

// final BN+ReLU (layer 11 -> d_out)
__global__ void k_bnrelu(const float* __restrict__ f, const float* __restrict__ sums,
                         const float* __restrict__ g, const float* __restrict__ b,
                         int n, int C, float* __restrict__ out) {
    __shared__ float ssc[128], ssh[128];
    int tid = threadIdx.x;
    if (tid < C) {
        float inv = 1.f / (float)n;
        float mu  = sums[tid] * inv;
        float var = sums[C + tid] * inv - mu * mu;
        float sc  = g[tid] * rsqrtf(var + 0.001f);
        ssc[tid] = sc;
        ssh[tid] = b[tid] - mu * sc;
    }
    __syncthreads();
    int total = n * C;
    for (int idx = blockIdx.x * blockDim.x + tid; idx < total;
         idx += gridDim.x * blockDim.x) {
        int c = idx & (C - 1);
        float v = f[idx] * ssc[c] + ssh[c];
        out[idx] = v > 0.f ? v : 0.f;
    }
}

// ---------------- host orchestration ----------------------------------------
template<int CIN, int COUT, int CT, int PBLK, int TAPS, bool WS, int THREADS>
static void launch_conv(const float* fin, float* fout, const int* nb,
                        const float* wt, const float* psum, const float* pg,
                        const float* pb, int n_prev, float* sums, int n_out) {
    int ppb = (THREADS / CT) * PBLK;
    int nblk = (n_out + ppb - 1) / ppb;
    k_conv_t<CIN, COUT, CT, PBLK, TAPS, WS, THREADS><<<nblk, THREADS>>>(
        fin, fout, nb, wt, psum, pg, pb, n_prev, sums, n_out);
}

extern "C" void kernel_launch(void* const* d_in, const int* in_sizes, int n_in,
                              void* d_out, int out_size) {
    const float* vf    = (const float*)d_in[0];
    const float* gamma = (const float*)d_in[13];
    const float* beta  = (const float*)d_in[14];
    const int* coords[5];
    int np[5];
    for (int i = 0; i < 5; i++) {
        coords[i] = (const int*)d_in[15 + i];
        np[i]     = in_sizes[15 + i] / 4;
    }

    void* pv;
    cudaGetSymbolAddress(&pv, g_grid); int*   grid = (int*)pv;
    cudaGetSymbolAddress(&pv, g_bufA); float* bufA = (float*)pv;
    cudaGetSymbolAddress(&pv, g_bufB); float* bufB = (float*)pv;
    cudaGetSymbolAddress(&pv, g_sums); float* sums = (float*)pv;
    cudaGetSymbolAddress(&pv, g_wT);   float* wT   = (float*)pv;
    cudaGetSymbolAddress(&pv, g_nb);   int*   nb   = (int*)pv;

    static const int CO[12]   = {16,16,32,32,32,64,64,64,64,64,64,128};
    static const int OFFc[12] = {0,16,32,64,96,128,192,256,320,384,448,512};
    static const int SHP[4][3] = {{41,160,160},{21,80,80},{11,40,40},{5,20,20}};

    long goff[4];
    goff[0] = 0;
    for (int s = 0; s < 3; s++)
        goff[s + 1] = goff[s] + 2L * SHP[s][0] * SHP[s][1] * SHP[s][2];

    // weight offsets (fixed layer dims)
    static const int CIw[12] = {4,16,16,32,32,32,64,64,64,64,64,64};
    static const int TPw[12] = {27,27,27,27,27,27,27,27,27,27,27,3};
    long woff[13];
    woff[0] = 0;
    for (int l = 0; l < 12; l++)
        woff[l + 1] = woff[l] + (long)TPw[l] * CIw[l] * CO[l];

    // #1: weight transpose + stats zeroing
    WPtrs wp;
    for (int l = 0; l < 12; l++) wp.w[l] = (const float*)d_in[1 + l];
    k_wtrans_all<<<(WTOT + 12 * 256 + 255) / 256, 256>>>(wp, wT, sums);

    // #2: all scatters fused
    ScAll sa;
    sa.base[0] = 0;
    for (int s = 0; s < 4; s++) {
        sa.coords[s] = (const int4*)coords[s];
        sa.grid[s]   = grid + goff[s];
        sa.D[s] = SHP[s][0]; sa.H[s] = SHP[s][1]; sa.W[s] = SHP[s][2];
        sa.base[s + 1] = sa.base[s] + np[s];
    }
    int sctot = sa.base[4];
    k_scatter_all<<<(sctot + 255) / 256, 256>>>(sa, sctot);

    // #3: all neighbor maps fused (point-major)
    static const int cfgIn[8]  = {0, 0, 1, 1, 2, 2, 3, 3};
    static const int cfgOut[8] = {0, 1, 1, 2, 2, 3, 3, 4};
    static const int cfgKH[8]  = {3, 3, 3, 3, 3, 3, 3, 1};
    static const int cfgKW[8]  = {3, 3, 3, 3, 3, 3, 3, 1};
    static const int cfgS[8][3] = {{1,1,1},{2,2,2},{1,1,1},{2,2,2},
                                   {1,1,1},{2,2,2},{1,1,1},{2,1,1}};
    static const int cfgP[8][3] = {{1,1,1},{1,1,1},{1,1,1},{1,1,1},
                                   {1,1,1},{0,1,1},{1,1,1},{0,0,0}};
    NbAll na;
    long nbo[9];
    nbo[0] = 0;
    na.base[0] = 0;
    for (int c = 0; c < 8; c++) {
        int s = cfgIn[c];
        int taps = 3 * cfgKH[c] * cfgKW[c];
        na.c[c].outc  = (const int4*)coords[cfgOut[c]];
        na.c[c].inc   = (const int4*)coords[s];
        na.c[c].grid  = grid + goff[s];
        na.c[c].nboff = nbo[c];
        na.c[c].n_out = np[cfgOut[c]];
        na.c[c].KH = cfgKH[c]; na.c[c].KW = cfgKW[c];
        na.c[c].sz = cfgS[c][0]; na.c[c].sy = cfgS[c][1]; na.c[c].sx = cfgS[c][2];
        na.c[c].pz = cfgP[c][0]; na.c[c].py = cfgP[c][1]; na.c[c].px = cfgP[c][2];
        na.c[c].D = SHP[s][0]; na.c[c].H = SHP[s][1]; na.c[c].W = SHP[s][2];
        nbo[c + 1] = nbo[c] + (long)taps * np[cfgOut[c]];
        na.base[c + 1] = na.base[c] + np[cfgOut[c]];
    }
    int nbtot = na.base[8];
    k_nbmap_all<<<(nbtot + 127) / 128, 128>>>(na, nbtot, nb);

    // per-layer map index
    static const int LMAP[12] = {0, 0, 1, 2, 2, 3, 4, 4, 5, 6, 6, 7};
    static const int ICX[12]  = {0,0,0,1,1,1,2,2,2,3,3,3};
    static const int OCX[12]  = {0,0,1,1,1,2,2,2,3,3,3,4};

    const float* cur = vf;
    float* bufs[2] = {bufA, bufB};
    int cb = 0;

    for (int l = 0; l < 12; l++) {
        int nin  = np[ICX[l]];
        int nout = np[OCX[l]];
        const int* lnb = nb + nbo[LMAP[l]];

        float* outb = bufs[cb];
        const float* psum = (l == 0) ? sums : sums + (l - 1) * 256;
        const float* pg   = (l == 0) ? gamma : gamma + OFFc[l - 1];
        const float* pb   = (l == 0) ? beta  : beta  + OFFc[l - 1];
        int n_prev        = (l == 0) ? 0 : nin;
        float* msum       = sums + l * 256;
        const float* wt   = wT + woff[l];

        // round-13 config (proven 1086us) + L8-L10 moved to 256 threads
        // (halves their weight-panel traffic; regs unchanged)
        switch (l) {
        case 0:  launch_conv< 4, 16, 16, 2, 27, false, 128>(cur, outb, lnb, wt, psum, pg, pb, n_prev, msum, nout); break;
        case 1:  launch_conv<16, 16, 16, 2, 27, false, 128>(cur, outb, lnb, wt, psum, pg, pb, n_prev, msum, nout); break;
        case 2:  launch_conv<16, 32, 16, 4, 27, true , 256>(cur, outb, lnb, wt, psum, pg, pb, n_prev, msum, nout); break;
        case 3:  launch_conv<32, 32, 16, 8, 27, true , 256>(cur, outb, lnb, wt, psum, pg, pb, n_prev, msum, nout); break;
        case 4:  launch_conv<32, 32, 16, 8, 27, true , 256>(cur, outb, lnb, wt, psum, pg, pb, n_prev, msum, nout); break;
        case 5:  launch_conv<32, 64, 16, 4, 27, true , 256>(cur, outb, lnb, wt, psum, pg, pb, n_prev, msum, nout); break;
        case 6:  launch_conv<64, 64, 16, 4, 27, true , 256>(cur, outb, lnb, wt, psum, pg, pb, n_prev, msum, nout); break;
        case 7:  launch_conv<64, 64, 16, 4, 27, true , 256>(cur, outb, lnb, wt, psum, pg, pb, n_prev, msum, nout); break;
        case 8:  launch_conv<64, 64, 16, 2, 27, true , 256>(cur, outb, lnb, wt, psum, pg, pb, n_prev, msum, nout); break;
        case 9:  launch_conv<64, 64, 16, 2, 27, true , 256>(cur, outb, lnb, wt, psum, pg, pb, n_prev, msum, nout); break;
        case 10: launch_conv<64, 64, 16, 2, 27, true , 256>(cur, outb, lnb, wt, psum, pg, pb, n_prev, msum, nout); break;
        case 11: launch_conv<64,128, 16, 1,  3, true , 128>(cur, outb, lnb, wt, psum, pg, pb, n_prev, msum, nout); break;
        }

        cur = outb;
        cb ^= 1;
    }

    // final BN+ReLU of layer 11 into d_out
    int n5 = np[4];
    int total = n5 * 128;
    int bblk = (total + 255) / 256;
    if (bblk > 2048) bblk = 2048;
    k_bnrelu<<<bblk, 256>>>(cur, sums + 11 * 256, gamma + OFFc[11], beta + OFFc[11],
                            n5, 128, (float*)d_out);
}